// round 15
// baseline (speedup 1.0000x reference)
#include <cuda_runtime.h>
#include <cstdint>
#include <math.h>

// Problem constants
#define B_   8
#define T_   4
#define C_   512
#define H_   32
#define W_   32
#define HW_  1024
#define BT_  32          // B_*T_
#define NPART 64         // channel partitions per t (= producer blocks per t)
#define CPP   (C_/NPART) // 8 channels per block
#define HP_  28
#define WP_  28
#define NP_  784         // 28*28
#define BN_EPS 1e-5f
#define BSTRIDE ((size_t)T_ * C_ * HW_)   // elements between consecutive b
#define BSTR4   (BSTRIDE/4)               // in float4 units
#define NTHR 512

// Scratch (allocation-free rule: __device__ globals; zero-init at load)
__device__ float g_part[NPART][BT_ * HW_];   // 8 MB
__device__ int   g_cnt[T_];                  // producer completion per t
__device__ int   g_done[T_];                 // tail completion per t

// ---------------------------------------------------------------------------
// Single fused kernel: ONE DRAM pass + hot-L2 re-read + in-kernel tail.
// grid: 256 blocks (2/SM), 512 threads.
// Producer phase (all blocks): 8 channels; per channel stats -> 1 barrier ->
//   A,B,D -> d^2 from hot L2; write partials; fence; count.
// Tail phase (blocks with p<8, one per bt): spin until all 64 producers of
//   this t are done, then layer-sum (L2-hot), 5x5 window, sqrt, max +
//   first-occurrence argmin, write outputs. Counters self-reset (done[t]).
// beta cancels exactly in (l_bn - r_bn).
// Output layout (float32, tuple order):
//   [0,32) values (B,T) | [32,96) coords (B,T,2) [x,y] | [96,25184) heatmap
// ---------------------------------------------------------------------------
__global__ __launch_bounds__(NTHR, 2) void fused_kernel(
    const float* __restrict__ l, const float* __restrict__ r,
    const float* __restrict__ gamma, float* __restrict__ out)
{
    const int t   = blockIdx.x >> 6;        // / NPART
    const int p   = blockIdx.x & (NPART-1);
    const int tid = threadIdx.x;
    const int lane = tid & 31;
    const int wid  = tid >> 5;              // 0..15

    int bvec[4], hw4[4];
    size_t offb[4];
    #pragma unroll
    for (int i = 0; i < 4; i++) {
        const int s = tid + i * NTHR;
        bvec[i] = s >> 8;
        hw4[i]  = s & 255;
        offb[i] = (size_t)bvec[i] * BSTR4 + hw4[i];
    }

    __shared__ float w0[2][16], w1[2][16], w2[2][16], w3[2][16];
    __shared__ float sgamma[CPP];
    if (tid < CPP) sgamma[tid] = gamma[p * CPP + tid];

    float acc[16];
    #pragma unroll
    for (int k = 0; k < 16; k++) acc[k] = 0.f;

    const float4* l4 = reinterpret_cast<const float4*>(l);
    const float4* r4 = reinterpret_cast<const float4*>(r);

    #pragma unroll 1
    for (int ci = 0; ci < CPP; ci++) {
        const int c = p * CPP + ci;
        const size_t chbase = ((size_t)(t * C_ + c)) * (HW_ / 4);

        // ---- stats pass: stream 4+4 float4, accumulate
        float sl = 0.f, ql = 0.f, sr = 0.f, qr = 0.f;
        #pragma unroll
        for (int i = 0; i < 4; i++) {
            float4 lv = l4[offb[i] + chbase];
            float4 rv = r4[offb[i] + chbase];
            sl += (lv.x + lv.y) + (lv.z + lv.w);
            sr += (rv.x + rv.y) + (rv.z + rv.w);
            ql = fmaf(lv.x, lv.x, ql); ql = fmaf(lv.y, lv.y, ql);
            ql = fmaf(lv.z, lv.z, ql); ql = fmaf(lv.w, lv.w, ql);
            qr = fmaf(rv.x, rv.x, qr); qr = fmaf(rv.y, rv.y, qr);
            qr = fmaf(rv.z, rv.z, qr); qr = fmaf(rv.w, rv.w, qr);
        }

        // ---- prefetch next channel to L2 (flies during barrier + d^2)
        if (ci + 1 < CPP) {
            const size_t nb = chbase + (HW_ / 4);
            #pragma unroll
            for (int i = 0; i < 4; i++) {
                asm volatile("prefetch.global.L2 [%0];" :: "l"(l4 + offb[i] + nb));
                asm volatile("prefetch.global.L2 [%0];" :: "l"(r4 + offb[i] + nb));
            }
        }

        // ---- warp shuffle reduction
        #pragma unroll
        for (int o = 16; o > 0; o >>= 1) {
            sl += __shfl_xor_sync(0xffffffffu, sl, o);
            ql += __shfl_xor_sync(0xffffffffu, ql, o);
            sr += __shfl_xor_sync(0xffffffffu, sr, o);
            qr += __shfl_xor_sync(0xffffffffu, qr, o);
        }

        const int par = ci & 1;
        if (lane == 0) {
            w0[par][wid] = sl; w1[par][wid] = ql;
            w2[par][wid] = sr; w3[par][wid] = qr;
        }
        __syncthreads();

        // ---- every warp combines the 16 warp-sums
        float a0 = (lane < 16) ? w0[par][lane] : 0.f;
        float a1 = (lane < 16) ? w1[par][lane] : 0.f;
        float a2 = (lane < 16) ? w2[par][lane] : 0.f;
        float a3 = (lane < 16) ? w3[par][lane] : 0.f;
        #pragma unroll
        for (int o = 8; o > 0; o >>= 1) {
            a0 += __shfl_xor_sync(0xffffffffu, a0, o);
            a1 += __shfl_xor_sync(0xffffffffu, a1, o);
            a2 += __shfl_xor_sync(0xffffffffu, a2, o);
            a3 += __shfl_xor_sync(0xffffffffu, a3, o);
        }
        a0 = __shfl_sync(0xffffffffu, a0, 0);
        a1 = __shfl_sync(0xffffffffu, a1, 0);
        a2 = __shfl_sync(0xffffffffu, a2, 0);
        a3 = __shfl_sync(0xffffffffu, a3, 0);

        const float inv_n = 1.f / (float)(B_ * HW_);   // 1/8192
        float mul  = a0 * inv_n;
        float mur  = a2 * inv_n;
        float varl = fmaf(-mul, mul, a1 * inv_n);
        float varr = fmaf(-mur, mur, a3 * inv_n);
        float g  = sgamma[ci];
        float A  = g / sqrtf(varl + BN_EPS);
        float Bc = g / sqrtf(varr + BN_EPS);
        float D  = A * mul - Bc * mur;

        // ---- d^2 pass: re-read same data (hot in L2), accumulate
        #pragma unroll
        for (int i = 0; i < 4; i++) {
            float4 lv = l4[offb[i] + chbase];
            float4 rv = r4[offb[i] + chbase];
            float d;
            d = fmaf(A, lv.x, fmaf(-Bc, rv.x, -D)); acc[i*4+0] = fmaf(d, d, acc[i*4+0]);
            d = fmaf(A, lv.y, fmaf(-Bc, rv.y, -D)); acc[i*4+1] = fmaf(d, d, acc[i*4+1]);
            d = fmaf(A, lv.z, fmaf(-Bc, rv.z, -D)); acc[i*4+2] = fmaf(d, d, acc[i*4+2]);
            d = fmaf(A, lv.w, fmaf(-Bc, rv.w, -D)); acc[i*4+3] = fmaf(d, d, acc[i*4+3]);
        }
    }

    // ---- write partials
    float4* gp = reinterpret_cast<float4*>(g_part[p]);
    #pragma unroll
    for (int i = 0; i < 4; i++) {
        gp[(bvec[i] * T_ + t) * (HW_/4) + hw4[i]] =
            make_float4(acc[i*4+0], acc[i*4+1], acc[i*4+2], acc[i*4+3]);
    }

    // ---- producer completion (release)
    __threadfence();
    __syncthreads();
    if (tid == 0) atomicAdd(&g_cnt[t], 1);

    // ======================= tail phase (p < 8) ============================
    if (p >= B_) return;
    const int bt = p * T_ + t;      // b = p

    // spin until all 64 producers of this t are done
    if (tid == 0) {
        while (atomicAdd(&g_cnt[t], 0) < NPART) __nanosleep(128);
    }
    __syncthreads();
    __threadfence();                 // acquire: partials now visible

    __shared__ float4 sred[4][256];  // 16 KB
    __shared__ float  d2[HW_];       // 4 KB
    __shared__ float  smx[NTHR];
    __shared__ unsigned long long smn[NTHR];

    // Phase A: layer-sum. thread = (lg = tid>>7 in [0,4), j = tid&127).
    // Each thread: 2 float4 positions x 16 layers = 32 independent LDG.128.
    {
        const int lg = tid >> 7;
        const int j  = tid & 127;
        const int base4 = bt * (HW_ / 4);
        #pragma unroll
        for (int q = 0; q < 2; q++) {
            const int p4 = j * 2 + q;
            float4 a = make_float4(0.f, 0.f, 0.f, 0.f);
            #pragma unroll
            for (int k = 0; k < 16; k++) {
                const float4 v =
                    reinterpret_cast<const float4*>(g_part[lg * 16 + k])[base4 + p4];
                a.x += v.x; a.y += v.y; a.z += v.z; a.w += v.w;
            }
            sred[lg][p4] = a;
        }
    }
    __syncthreads();

    // Phase B: combine 4 layer-groups
    if (tid < 256) {
        float4 a = sred[0][tid], b = sred[1][tid], c = sred[2][tid], e = sred[3][tid];
        d2[tid * 4 + 0] = (a.x + b.x) + (c.x + e.x);
        d2[tid * 4 + 1] = (a.y + b.y) + (c.y + e.y);
        d2[tid * 4 + 2] = (a.z + b.z) + (c.z + e.z);
        d2[tid * 4 + 3] = (a.w + b.w) + (c.w + e.w);
    }
    __syncthreads();

    // Phase C: windows (784 positions over 512 threads)
    float mymax = 0.f;                               // hm >= 0
    unsigned long long myenc = 0xFFFFFFFFFFFFFFFFULL;
    for (int w = tid; w < NP_; w += NTHR) {
        const int y = w / WP_;
        const int x = w % WP_;
        float ws = 0.f;
        #pragma unroll
        for (int dy = 0; dy < 5; dy++)
            #pragma unroll
            for (int dx = 0; dx < 5; dx++)
                ws += d2[(y + dy) * W_ + (x + dx)];
        const float hm = sqrtf(ws / 25.0f);
        out[96 + bt * NP_ + w] = hm;
        mymax = fmaxf(mymax, hm);
        const unsigned long long enc =
            ((unsigned long long)__float_as_uint(hm) << 32) | (unsigned int)w;
        if (enc < myenc) myenc = enc;
    }

    smx[tid] = mymax; smn[tid] = myenc;
    __syncthreads();
    for (int st = NTHR / 2; st > 0; st >>= 1) {
        if (tid < st) {
            smx[tid] = fmaxf(smx[tid], smx[tid + st]);
            if (smn[tid + st] < smn[tid]) smn[tid] = smn[tid + st];
        }
        __syncthreads();
    }

    if (tid == 0) {
        out[bt] = smx[0];
        const int idx = (int)(smn[0] & 0xFFFFFFFFULL);
        out[32 + bt * 2 + 0] = (float)(idx % WP_);  // x_argmin
        out[32 + bt * 2 + 1] = (float)(idx / WP_);  // y_argmin

        // counter self-reset: last tail block of this t clears both counters
        const int d = atomicAdd(&g_done[t], 1);
        if (d == B_ - 1) {
            g_cnt[t]  = 0;
            g_done[t] = 0;
            __threadfence();
        }
    }
}

// ---------------------------------------------------------------------------
extern "C" void kernel_launch(void* const* d_in, const int* in_sizes, int n_in,
                              void* d_out, int out_size)
{
    const float* l     = (const float*)d_in[0];
    const float* r     = (const float*)d_in[1];
    const float* gamma = (const float*)d_in[2];
    // d_in[3] = bn_beta: cancels exactly in (l_bn - r_bn), unused.
    float* out = (float*)d_out;

    fused_kernel<<<T_ * NPART, NTHR>>>(l, r, gamma, out);
}

// round 16
// speedup vs baseline: 1.0189x; 1.0189x over previous
#include <cuda_runtime.h>
#include <cstdint>
#include <math.h>

// Problem constants
#define B_   8
#define T_   4
#define C_   512
#define H_   32
#define W_   32
#define HW_  1024
#define BT_  32          // B_*T_
#define NPART 64         // channel partitions per t
#define CPP   (C_/NPART) // 8 channels per block
#define HP_  28
#define WP_  28
#define NP_  784         // 28*28
#define BN_EPS 1e-5f
#define BSTRIDE ((size_t)T_ * C_ * HW_)   // elements between consecutive b
#define BSTR4   (BSTRIDE/4)               // in float4 units
#define NTHR 512

// Scratch (allocation-free rule: __device__ globals)
__device__ float g_part[NPART][BT_ * HW_];   // 8 MB
__device__ float g_d2[BT_ * HW_];            // 128 KB

// ---------------------------------------------------------------------------
// Fused kernel (R14 structure): ONE DRAM pass + hot-L2 re-read + L2 prefetch
// of the next channel issued before the barrier (covers reduction + d^2
// dead time with DRAM traffic).
// grid: T_*NPART = 256 blocks (2/SM), 512 threads.
// beta cancels exactly in (l_bn - r_bn).
// ---------------------------------------------------------------------------
__global__ __launch_bounds__(NTHR, 2) void fused_kernel(
    const float* __restrict__ l, const float* __restrict__ r,
    const float* __restrict__ gamma)
{
    const int t   = blockIdx.x >> 6;        // / NPART
    const int p   = blockIdx.x & (NPART-1);
    const int tid = threadIdx.x;
    const int lane = tid & 31;
    const int wid  = tid >> 5;              // 0..15

    int bvec[4], hw4[4];
    size_t offb[4];
    #pragma unroll
    for (int i = 0; i < 4; i++) {
        const int s = tid + i * NTHR;
        bvec[i] = s >> 8;
        hw4[i]  = s & 255;
        offb[i] = (size_t)bvec[i] * BSTR4 + hw4[i];
    }

    __shared__ float w0[2][16], w1[2][16], w2[2][16], w3[2][16];
    __shared__ float sgamma[CPP];
    if (tid < CPP) sgamma[tid] = gamma[p * CPP + tid];

    float acc[16];
    #pragma unroll
    for (int k = 0; k < 16; k++) acc[k] = 0.f;

    const float4* l4 = reinterpret_cast<const float4*>(l);
    const float4* r4 = reinterpret_cast<const float4*>(r);

    #pragma unroll 1
    for (int ci = 0; ci < CPP; ci++) {
        const int c = p * CPP + ci;
        const size_t chbase = ((size_t)(t * C_ + c)) * (HW_ / 4);

        // ---- stats pass: stream 4+4 float4, accumulate
        float sl = 0.f, ql = 0.f, sr = 0.f, qr = 0.f;
        #pragma unroll
        for (int i = 0; i < 4; i++) {
            float4 lv = l4[offb[i] + chbase];
            float4 rv = r4[offb[i] + chbase];
            sl += (lv.x + lv.y) + (lv.z + lv.w);
            sr += (rv.x + rv.y) + (rv.z + rv.w);
            ql = fmaf(lv.x, lv.x, ql); ql = fmaf(lv.y, lv.y, ql);
            ql = fmaf(lv.z, lv.z, ql); ql = fmaf(lv.w, lv.w, ql);
            qr = fmaf(rv.x, rv.x, qr); qr = fmaf(rv.y, rv.y, qr);
            qr = fmaf(rv.z, rv.z, qr); qr = fmaf(rv.w, rv.w, qr);
        }

        // ---- prefetch next channel to L2 (flies during barrier + d^2)
        if (ci + 1 < CPP) {
            const size_t nb = chbase + (HW_ / 4);
            #pragma unroll
            for (int i = 0; i < 4; i++) {
                asm volatile("prefetch.global.L2 [%0];" :: "l"(l4 + offb[i] + nb));
                asm volatile("prefetch.global.L2 [%0];" :: "l"(r4 + offb[i] + nb));
            }
        }

        // ---- warp shuffle reduction
        #pragma unroll
        for (int o = 16; o > 0; o >>= 1) {
            sl += __shfl_xor_sync(0xffffffffu, sl, o);
            ql += __shfl_xor_sync(0xffffffffu, ql, o);
            sr += __shfl_xor_sync(0xffffffffu, sr, o);
            qr += __shfl_xor_sync(0xffffffffu, qr, o);
        }

        const int par = ci & 1;
        if (lane == 0) {
            w0[par][wid] = sl; w1[par][wid] = ql;
            w2[par][wid] = sr; w3[par][wid] = qr;
        }
        __syncthreads();   // the ONLY barrier per channel

        // ---- every warp combines the 16 warp-sums
        float a0 = (lane < 16) ? w0[par][lane] : 0.f;
        float a1 = (lane < 16) ? w1[par][lane] : 0.f;
        float a2 = (lane < 16) ? w2[par][lane] : 0.f;
        float a3 = (lane < 16) ? w3[par][lane] : 0.f;
        #pragma unroll
        for (int o = 8; o > 0; o >>= 1) {
            a0 += __shfl_xor_sync(0xffffffffu, a0, o);
            a1 += __shfl_xor_sync(0xffffffffu, a1, o);
            a2 += __shfl_xor_sync(0xffffffffu, a2, o);
            a3 += __shfl_xor_sync(0xffffffffu, a3, o);
        }
        a0 = __shfl_sync(0xffffffffu, a0, 0);
        a1 = __shfl_sync(0xffffffffu, a1, 0);
        a2 = __shfl_sync(0xffffffffu, a2, 0);
        a3 = __shfl_sync(0xffffffffu, a3, 0);

        const float inv_n = 1.f / (float)(B_ * HW_);   // 1/8192
        float mul  = a0 * inv_n;
        float mur  = a2 * inv_n;
        float varl = fmaf(-mul, mul, a1 * inv_n);
        float varr = fmaf(-mur, mur, a3 * inv_n);
        float g  = sgamma[ci];
        float A  = g / sqrtf(varl + BN_EPS);
        float Bc = g / sqrtf(varr + BN_EPS);
        float D  = A * mul - Bc * mur;

        // ---- d^2 pass: re-read same data (hot in L2), accumulate
        #pragma unroll
        for (int i = 0; i < 4; i++) {
            float4 lv = l4[offb[i] + chbase];
            float4 rv = r4[offb[i] + chbase];
            float d;
            d = fmaf(A, lv.x, fmaf(-Bc, rv.x, -D)); acc[i*4+0] = fmaf(d, d, acc[i*4+0]);
            d = fmaf(A, lv.y, fmaf(-Bc, rv.y, -D)); acc[i*4+1] = fmaf(d, d, acc[i*4+1]);
            d = fmaf(A, lv.z, fmaf(-Bc, rv.z, -D)); acc[i*4+2] = fmaf(d, d, acc[i*4+2]);
            d = fmaf(A, lv.w, fmaf(-Bc, rv.w, -D)); acc[i*4+3] = fmaf(d, d, acc[i*4+3]);
        }
    }

    // ---- write partials: g_part[p][(b*T+t)*1024 + hw] as float4
    float4* gp = reinterpret_cast<float4*>(g_part[p]);
    #pragma unroll
    for (int i = 0; i < 4; i++) {
        gp[(bvec[i] * T_ + t) * (HW_/4) + hw4[i]] =
            make_float4(acc[i*4+0], acc[i*4+1], acc[i*4+2], acc[i*4+3]);
    }
}

// ---------------------------------------------------------------------------
// Reduce: collapse 64 partials -> g_d2. grid: 256 blocks (bt x 8 segments),
// 1024 threads as (kg = tid>>7 in [0,8), hw_local = tid&127). Each thread
// sums 8 partitions; smem combine of 8 groups. Deterministic order.
// ---------------------------------------------------------------------------
__global__ __launch_bounds__(1024) void reduce_kernel()
{
    const int bt = blockIdx.x >> 3;
    const int q  = blockIdx.x & 7;
    const int hw_local = threadIdx.x & 127;
    const int kg = threadIdx.x >> 7;          // 0..7
    const int hw = q * 128 + hw_local;

    float s = 0.f;
    #pragma unroll
    for (int i = 0; i < 8; i++)
        s += g_part[kg * 8 + i][bt * HW_ + hw];

    __shared__ float red[8][128];
    red[kg][hw_local] = s;
    __syncthreads();

    if (kg == 0) {
        float tot = 0.f;
        #pragma unroll
        for (int k = 0; k < 8; k++) tot += red[k][hw_local];
        g_d2[bt * HW_ + hw] = tot;
    }
}

// ---------------------------------------------------------------------------
// Finalize: 5x5 window sum, sqrt, max + first-argmin.
// grid: 32 blocks (one per (b,t)), 1024 threads.
// Output layout (float32, tuple order):
//   [0,32) values (B,T) | [32,96) coords (B,T,2) [x,y] | [96,25184) heatmap
// ---------------------------------------------------------------------------
__global__ __launch_bounds__(1024) void finalize_kernel(float* __restrict__ out)
{
    const int bt  = blockIdx.x;
    const int tid = threadIdx.x;

    __shared__ float d2[HW_];
    d2[tid] = g_d2[bt * HW_ + tid];
    __syncthreads();

    float mymax = -3.0e38f;
    float mymin =  3.0e38f;
    int   myidx = 0x7fffffff;

    if (tid < NP_) {
        const int y = tid / WP_;
        const int x = tid % WP_;
        float ws = 0.f;
        #pragma unroll
        for (int dy = 0; dy < 5; dy++)
            #pragma unroll
            for (int dx = 0; dx < 5; dx++)
                ws += d2[(y + dy) * W_ + (x + dx)];
        float hm = sqrtf(ws / 25.0f);
        out[96 + bt * NP_ + tid] = hm;
        mymax = hm; mymin = hm; myidx = tid;
    }

    __shared__ float smx[1024];
    __shared__ float smn[1024];
    __shared__ int   six[1024];
    smx[tid] = mymax; smn[tid] = mymin; six[tid] = myidx;
    __syncthreads();
    for (int st = 512; st > 0; st >>= 1) {
        if (tid < st) {
            smx[tid] = fmaxf(smx[tid], smx[tid + st]);
            float v = smn[tid + st];
            int  ix = six[tid + st];
            if (v < smn[tid] || (v == smn[tid] && ix < six[tid])) {
                smn[tid] = v; six[tid] = ix;
            }
        }
        __syncthreads();
    }

    if (tid == 0) {
        out[bt] = smx[0];
        int idx = six[0];
        out[32 + bt * 2 + 0] = (float)(idx % WP_);  // x_argmin
        out[32 + bt * 2 + 1] = (float)(idx / WP_);  // y_argmin
    }
}

// ---------------------------------------------------------------------------
extern "C" void kernel_launch(void* const* d_in, const int* in_sizes, int n_in,
                              void* d_out, int out_size)
{
    const float* l     = (const float*)d_in[0];
    const float* r     = (const float*)d_in[1];
    const float* gamma = (const float*)d_in[2];
    // d_in[3] = bn_beta: cancels exactly in (l_bn - r_bn), unused.
    float* out = (float*)d_out;

    fused_kernel<<<T_ * NPART, NTHR>>>(l, r, gamma);
    reduce_kernel<<<BT_ * 8, 1024>>>();
    finalize_kernel<<<BT_, 1024>>>(out);
}